// round 15
// baseline (speedup 1.0000x reference)
#include <cuda_runtime.h>
#include <cuda_fp16.h>
#include <cstdint>

// Problem constants
#define BATCH   524288
#define KDIM    128     // in_features (K)
#define NOUT    128     // out_features
#define TILE_M  32      // batch rows per CTA tile (3 CTAs/SM)
#define NTILES  (BATCH / TILE_M)   // 16384
#define THREADS 128     // 4 warps; each warp = 32 rows x 32 outs
#define CTAS_PER_SM 3

#define XBUF_BYTES (TILE_M * KDIM * 2)     // 8192 per fp16 input buffer
#define OBUF_OFF   (2 * XBUF_BYTES)        // 16384
#define OBUF_BYTES (TILE_M * NOUT * 4)     // 16384 fp32 staging for output tile
#define SMEM_TOTAL (OBUF_OFF + OBUF_BYTES) // 32768

// Swizzle for 256B x-tile rows: XOR row%8 (addr bits [8:10]) into 16B-chunk bits [4:6].
static __device__ __forceinline__ uint32_t sw(uint32_t a) {
    return a ^ ((a >> 4) & 0x70u);
}
// Swizzle for 512B output rows: XOR row%8 (addr bits [9:11]) into 16B-chunk bits [4:6].
static __device__ __forceinline__ uint32_t swo(uint32_t a) {
    return a ^ ((a >> 5) & 0x70u);
}

static __device__ __forceinline__ uint32_t pack_h2(float a, float b) {
    __half2 h = __floats2half2_rn(a, b);
    return *reinterpret_cast<uint32_t*>(&h);
}

__global__ void __launch_bounds__(THREADS, CTAS_PER_SM) linear_hmma_kernel(
    const float* __restrict__ x, const float* __restrict__ w,
    const float* __restrict__ bias, float* __restrict__ out)
{
    extern __shared__ __align__(1024) char smem[];
    uint32_t sb = (uint32_t)__cvta_generic_to_shared(smem);

    const int tid   = threadIdx.x;
    const int lane  = tid & 31;
    const int warpN = tid >> 5;   // 0..3 : 32-out group (all warps share the 32 rows)
    const int g     = lane >> 2;  // groupID (0..7)
    const int tg    = lane & 3;   // thread-in-group (0..3)

    // ---- W fragments: fp32 -> fp16 once, pinned in registers for the whole run ----
    uint32_t wf[4][8][2];
#pragma unroll
    for (int nt = 0; nt < 4; ++nt) {
        const int n = warpN * 32 + nt * 8 + g;
        const float* wr = w + n * KDIM;
#pragma unroll
        for (int ks = 0; ks < 8; ++ks) {
            const int k0 = ks * 16 + tg * 2;
            wf[nt][ks][0] = pack_h2(__ldg(wr + k0),     __ldg(wr + k0 + 1));
            wf[nt][ks][1] = pack_h2(__ldg(wr + k0 + 8), __ldg(wr + k0 + 9));
        }
    }
    // bias for the coalesced store pass: lane covers 4 consecutive out features
    const float4 bias4 = *reinterpret_cast<const float4*>(bias + lane * 4);

    // ldmatrix x4 lane addressing
    const uint32_t lrow  = (uint32_t)(lane & 15);
    const uint32_t lcolb = (lane & 16) ? 16u : 0u;

    int tile = blockIdx.x;
    const int stride = gridDim.x;

    // ---- prologue: first x tile -> fp16 -> smem buf0 ----
    {
        const float4* s4 = reinterpret_cast<const float4*>(x + (size_t)tile * (TILE_M * KDIM));
#pragma unroll
        for (int i = 0; i < 8; ++i) {
            const int lin = i * THREADS + tid;
            const float4 v = __ldcs(s4 + lin);
            const uint32_t row = (uint32_t)(lin >> 5);
            const uint32_t k   = (uint32_t)((lin & 31) << 2);
            *reinterpret_cast<uint2*>(smem + sw(row * 256u + k * 2u)) =
                make_uint2(pack_h2(v.x, v.y), pack_h2(v.z, v.w));
        }
    }
    __syncthreads();

    int db = 0;
    while (tile < NTILES) {
        const int nxt = tile + stride;
        const bool more = nxt < NTILES;

        // 1) issue next tile's global loads first (latency hides under everything below)
        float4 pf[8];
        if (more) {
            const float4* s4 = reinterpret_cast<const float4*>(x + (size_t)nxt * (TILE_M * KDIM));
#pragma unroll
            for (int i = 0; i < 8; ++i) pf[i] = __ldcs(s4 + i * THREADS + tid);
        }

        // 2) compute current tile: 8 k-steps x (2 ldmatrix.x4 + 8 mma)
        float acc[2][4][4];
#pragma unroll
        for (int mt = 0; mt < 2; ++mt)
#pragma unroll
            for (int nt = 0; nt < 4; ++nt)
#pragma unroll
                for (int j = 0; j < 4; ++j) acc[mt][nt][j] = 0.0f;

        const uint32_t bufbase = sb + (uint32_t)db * XBUF_BYTES;
#pragma unroll
        for (int ks = 0; ks < 8; ++ks) {
            uint32_t a[2][4];
#pragma unroll
            for (int mt = 0; mt < 2; ++mt) {
                const uint32_t addr =
                    bufbase + sw((lrow + (uint32_t)mt * 16u) * 256u + (uint32_t)ks * 32u + lcolb);
                asm volatile(
                    "ldmatrix.sync.aligned.m8n8.x4.shared.b16 {%0,%1,%2,%3}, [%4];"
                    : "=r"(a[mt][0]), "=r"(a[mt][1]), "=r"(a[mt][2]), "=r"(a[mt][3])
                    : "r"(addr));
            }
#pragma unroll
            for (int mt = 0; mt < 2; ++mt)
#pragma unroll
                for (int nt = 0; nt < 4; ++nt)
                    asm volatile(
                        "mma.sync.aligned.m16n8k16.row.col.f32.f16.f16.f32 "
                        "{%0,%1,%2,%3}, {%4,%5,%6,%7}, {%8,%9}, {%0,%1,%2,%3};"
                        : "+f"(acc[mt][nt][0]), "+f"(acc[mt][nt][1]),
                          "+f"(acc[mt][nt][2]), "+f"(acc[mt][nt][3])
                        : "r"(a[mt][0]), "r"(a[mt][1]), "r"(a[mt][2]), "r"(a[mt][3]),
                          "r"(wf[nt][ks][0]), "r"(wf[nt][ks][1]));
        }

        // 3) stage accumulators into swizzled smem output buffer (no global scatter)
        {
            char* obuf = smem + OBUF_OFF;
#pragma unroll
            for (int mt = 0; mt < 2; ++mt) {
                const uint32_t r0 = (uint32_t)(mt * 16 + g);
#pragma unroll
                for (int nt = 0; nt < 4; ++nt) {
                    const uint32_t c = (uint32_t)(warpN * 32 + nt * 8 + tg * 2);
                    *reinterpret_cast<float2*>(obuf + swo(r0 * 512u + c * 4u)) =
                        make_float2(acc[mt][nt][0], acc[mt][nt][1]);
                    *reinterpret_cast<float2*>(obuf + swo((r0 + 8u) * 512u + c * 4u)) =
                        make_float2(acc[mt][nt][2], acc[mt][nt][3]);
                }
            }
        }
        __syncthreads();

        // 4) coalesced store pass: each warp-instruction writes one full 512B output row
        {
            const char* obuf = smem + OBUF_OFF;
            float* ob = out + (size_t)tile * (TILE_M * NOUT);
            const uint32_t c4 = (uint32_t)(lane * 16);   // byte offset within row
#pragma unroll
            for (int i = 0; i < 8; ++i) {
                const uint32_t row = (uint32_t)(i * 4 + warpN);
                float4 v = *reinterpret_cast<const float4*>(obuf + swo(row * 512u + c4));
                v.x += bias4.x; v.y += bias4.y; v.z += bias4.z; v.w += bias4.w;
                __stcs(reinterpret_cast<float4*>(ob + (size_t)row * NOUT + lane * 4), v);
            }
        }

        // 5) convert prefetched tile and store into the other x buffer
        if (more) {
            char* xb = smem + (db ^ 1) * XBUF_BYTES;
#pragma unroll
            for (int i = 0; i < 8; ++i) {
                const int lin = i * THREADS + tid;
                const uint32_t row = (uint32_t)(lin >> 5);
                const uint32_t k   = (uint32_t)((lin & 31) << 2);
                *reinterpret_cast<uint2*>(xb + sw(row * 256u + k * 2u)) =
                    make_uint2(pack_h2(pf[i].x, pf[i].y), pack_h2(pf[i].z, pf[i].w));
            }
        }

        __syncthreads();   // x buffer swap + obuf reuse barrier
        tile = nxt;
        db ^= 1;
    }
}

extern "C" void kernel_launch(void* const* d_in, const int* in_sizes, int n_in,
                              void* d_out, int out_size) {
    const float* x  = (const float*)d_in[0];   // enc_x  [524288, 128]
    const float* w  = (const float*)d_in[1];   // weight [128, 128]
    const float* b  = (const float*)d_in[2];   // bias   [128]
    float* out = (float*)d_out;                // [524288, 128] fp32

    int dev = 0;
    cudaGetDevice(&dev);
    int sms = 148;
    cudaDeviceGetAttribute(&sms, cudaDevAttrMultiProcessorCount, dev);

    cudaFuncSetAttribute(linear_hmma_kernel,
                         cudaFuncAttributeMaxDynamicSharedMemorySize, SMEM_TOTAL);

    linear_hmma_kernel<<<sms * CTAS_PER_SM, THREADS, SMEM_TOTAL>>>(x, w, b, out);
}

// round 16
// speedup vs baseline: 1.1785x; 1.1785x over previous
#include <cuda_runtime.h>
#include <cuda_fp16.h>
#include <cstdint>

// Problem constants
#define BATCH   524288
#define KDIM    128     // in_features (K)
#define NOUT    128     // out_features
#define TILE_M  32      // batch rows per CTA tile (3 CTAs/SM)
#define NTILES  (BATCH / TILE_M)   // 16384
#define THREADS 128     // 4 warps; each warp = 32 rows x 32 outs
#define CTAS_PER_SM 3

#define XBUF_BYTES (TILE_M * KDIM * 2)   // 8192 per fp16 buffer
#define SMEM_TOTAL (2 * XBUF_BYTES)      // 16384 (double buffer)

// Swizzle for 256B rows: XOR row%8 (addr bits [8:10]) into 16B-chunk bits [4:6].
static __device__ __forceinline__ uint32_t sw(uint32_t a) {
    return a ^ ((a >> 4) & 0x70u);
}

static __device__ __forceinline__ uint32_t pack_h2(float a, float b) {
    __half2 h = __floats2half2_rn(a, b);
    return *reinterpret_cast<uint32_t*>(&h);
}

__global__ void __launch_bounds__(THREADS, CTAS_PER_SM) linear_hmma_kernel(
    const float* __restrict__ x, const float* __restrict__ w,
    const float* __restrict__ bias, float* __restrict__ out)
{
    extern __shared__ __align__(1024) char smem[];
    uint32_t sb = (uint32_t)__cvta_generic_to_shared(smem);

    const int tid   = threadIdx.x;
    const int lane  = tid & 31;
    const int warpN = tid >> 5;   // 0..3 : 32-out group (all warps share the 32 rows)
    const int g     = lane >> 2;  // groupID (0..7)
    const int tg    = lane & 3;   // thread-in-group (0..3)

    // ---- W fragments: fp32 -> fp16 once, pinned in registers for the whole run ----
    uint32_t wf[4][8][2];
#pragma unroll
    for (int nt = 0; nt < 4; ++nt) {
        const int n = warpN * 32 + nt * 8 + g;
        const float* wr = w + n * KDIM;
#pragma unroll
        for (int ks = 0; ks < 8; ++ks) {
            const int k0 = ks * 16 + tg * 2;
            wf[nt][ks][0] = pack_h2(__ldg(wr + k0),     __ldg(wr + k0 + 1));
            wf[nt][ks][1] = pack_h2(__ldg(wr + k0 + 8), __ldg(wr + k0 + 9));
        }
    }
    // bias for this thread's output columns
    float bs[4][2];
#pragma unroll
    for (int nt = 0; nt < 4; ++nt) {
        const int c = warpN * 32 + nt * 8 + tg * 2;
        bs[nt][0] = __ldg(bias + c);
        bs[nt][1] = __ldg(bias + c + 1);
    }

    // ldmatrix x4 lane addressing
    const uint32_t lrow  = (uint32_t)(lane & 15);
    const uint32_t lcolb = (lane & 16) ? 16u : 0u;

    int tile = blockIdx.x;
    const int stride = gridDim.x;

    // ---- prologue: first x tile -> fp16 -> smem buf0 ----
    {
        const float4* s4 = reinterpret_cast<const float4*>(x + (size_t)tile * (TILE_M * KDIM));
#pragma unroll
        for (int i = 0; i < 8; ++i) {
            const int lin = i * THREADS + tid;
            const float4 v = __ldcs(s4 + lin);
            const uint32_t row = (uint32_t)(lin >> 5);
            const uint32_t k   = (uint32_t)((lin & 31) << 2);
            *reinterpret_cast<uint2*>(smem + sw(row * 256u + k * 2u)) =
                make_uint2(pack_h2(v.x, v.y), pack_h2(v.z, v.w));
        }
    }
    __syncthreads();

    int db = 0;
    while (tile < NTILES) {
        const int nxt = tile + stride;
        const bool more = nxt < NTILES;

        // 1) issue next tile's global loads first (latency hidden by MMA + epilogue)
        float4 pf[8];
        if (more) {
            const float4* s4 = reinterpret_cast<const float4*>(x + (size_t)nxt * (TILE_M * KDIM));
#pragma unroll
            for (int i = 0; i < 8; ++i) pf[i] = __ldcs(s4 + i * THREADS + tid);
        }

        // 2) compute current tile: software-pipelined ldmatrix (one k-step ahead)
        float acc[2][4][4];
#pragma unroll
        for (int mt = 0; mt < 2; ++mt)
#pragma unroll
            for (int nt = 0; nt < 4; ++nt)
#pragma unroll
                for (int j = 0; j < 4; ++j) acc[mt][nt][j] = 0.0f;

        const uint32_t bufbase = sb + (uint32_t)db * XBUF_BYTES;
        uint32_t a[2][2][4];   // [pipeline slot][mt][frag]

        // preload ks = 0 fragments
#pragma unroll
        for (int mt = 0; mt < 2; ++mt) {
            const uint32_t addr =
                bufbase + sw((lrow + (uint32_t)mt * 16u) * 256u + lcolb);
            asm volatile(
                "ldmatrix.sync.aligned.m8n8.x4.shared.b16 {%0,%1,%2,%3}, [%4];"
                : "=r"(a[0][mt][0]), "=r"(a[0][mt][1]), "=r"(a[0][mt][2]), "=r"(a[0][mt][3])
                : "r"(addr));
        }

#pragma unroll
        for (int ks = 0; ks < 8; ++ks) {
            const int cur = ks & 1;
            if (ks < 7) {
                const int nxtb = cur ^ 1;
#pragma unroll
                for (int mt = 0; mt < 2; ++mt) {
                    const uint32_t addr = bufbase +
                        sw((lrow + (uint32_t)mt * 16u) * 256u + (uint32_t)(ks + 1) * 32u + lcolb);
                    asm volatile(
                        "ldmatrix.sync.aligned.m8n8.x4.shared.b16 {%0,%1,%2,%3}, [%4];"
                        : "=r"(a[nxtb][mt][0]), "=r"(a[nxtb][mt][1]),
                          "=r"(a[nxtb][mt][2]), "=r"(a[nxtb][mt][3])
                        : "r"(addr));
                }
            }
#pragma unroll
            for (int mt = 0; mt < 2; ++mt)
#pragma unroll
                for (int nt = 0; nt < 4; ++nt)
                    asm volatile(
                        "mma.sync.aligned.m16n8k16.row.col.f32.f16.f16.f32 "
                        "{%0,%1,%2,%3}, {%4,%5,%6,%7}, {%8,%9}, {%0,%1,%2,%3};"
                        : "+f"(acc[mt][nt][0]), "+f"(acc[mt][nt][1]),
                          "+f"(acc[mt][nt][2]), "+f"(acc[mt][nt][3])
                        : "r"(a[cur][mt][0]), "r"(a[cur][mt][1]),
                          "r"(a[cur][mt][2]), "r"(a[cur][mt][3]),
                          "r"(wf[nt][ks][0]), "r"(wf[nt][ks][1]));
        }

        // 3) epilogue FIRST: acc depends on nothing pending -> writes flow while
        //    the prefetch LDGs are still in flight
        float* ob = out + (size_t)tile * (TILE_M * NOUT);
#pragma unroll
        for (int mt = 0; mt < 2; ++mt) {
            const int r0 = mt * 16 + g;
#pragma unroll
            for (int nt = 0; nt < 4; ++nt) {
                const int c = warpN * 32 + nt * 8 + tg * 2;
                float2 v0 = make_float2(acc[mt][nt][0] + bs[nt][0], acc[mt][nt][1] + bs[nt][1]);
                float2 v1 = make_float2(acc[mt][nt][2] + bs[nt][0], acc[mt][nt][3] + bs[nt][1]);
                __stcs(reinterpret_cast<float2*>(ob + (size_t)r0 * NOUT + c), v0);
                __stcs(reinterpret_cast<float2*>(ob + (size_t)(r0 + 8) * NOUT + c), v1);
            }
        }

        // 4) convert prefetched tile (LDG data has arrived by now) into other buffer
        if (more) {
            char* xb = smem + (db ^ 1) * XBUF_BYTES;
#pragma unroll
            for (int i = 0; i < 8; ++i) {
                const int lin = i * THREADS + tid;
                const uint32_t row = (uint32_t)(lin >> 5);
                const uint32_t k   = (uint32_t)((lin & 31) << 2);
                *reinterpret_cast<uint2*>(xb + sw(row * 256u + k * 2u)) =
                    make_uint2(pack_h2(pf[i].x, pf[i].y), pack_h2(pf[i].z, pf[i].w));
            }
        }

        __syncthreads();   // buffer swap barrier
        tile = nxt;
        db ^= 1;
    }
}

extern "C" void kernel_launch(void* const* d_in, const int* in_sizes, int n_in,
                              void* d_out, int out_size) {
    const float* x  = (const float*)d_in[0];   // enc_x  [524288, 128]
    const float* w  = (const float*)d_in[1];   // weight [128, 128]
    const float* b  = (const float*)d_in[2];   // bias   [128]
    float* out = (float*)d_out;                // [524288, 128] fp32

    int dev = 0;
    cudaGetDevice(&dev);
    int sms = 148;
    cudaDeviceGetAttribute(&sms, cudaDevAttrMultiProcessorCount, dev);

    cudaFuncSetAttribute(linear_hmma_kernel,
                         cudaFuncAttributeMaxDynamicSharedMemorySize, SMEM_TOTAL);

    linear_hmma_kernel<<<sms * CTAS_PER_SM, THREADS, SMEM_TOTAL>>>(x, w, b, out);
}